// round 6
// baseline (speedup 1.0000x reference)
#include <cuda_runtime.h>
#include <cuda_fp16.h>
#include <cstdint>

// ---------------- problem constants ----------------
#define KB      8
#define DIM     64
#define CB      1024
#define ROWS    8192
#define D_FULL  512
#define MT      128              // rows per CTA
#define NMT     (ROWS/MT)        // 64
#define NTHR    256
#define NCHUNK  8                // code chunks of 128

#define CODES_ELEMS (ROWS*KB*DIM)            // 4194304
#define INDS_OFF    CODES_ELEMS
#define COMMIT_OFF  (CODES_ELEMS + ROWS*KB)  // 4259840

// ---------------- device scratch ----------------
__device__ float  g_esq[KB*CB];
__device__ float  g_part[KB*NMT];
__device__ __half g_Bh[(size_t)KB*CB*DIM];   // 1 MB
__device__ __half g_Bl[(size_t)KB*CB*DIM];   // 1 MB

// ---------------- smem layout (bytes, dynamic) ----------------
#define SM_ESQ   0                 // 4096
#define SM_AH    4096              // 16384
#define SM_AL    20480             // 16384
#define SM_BH    36864             // 16384
#define SM_BL    53248             // 16384
#define SM_MB1   69632             // 2*128 floats
#define SM_MI1   70656
#define SM_MB2   71680
#define SM_MI2   72704
#define SM_RED   73728             // 256 floats
#define SM_TOTAL 74752

#define SWZ(bo) ((bo) ^ (((bo) >> 3) & 0x70))

// ---------------- helpers ----------------
__device__ __forceinline__ uint32_t smem_u32(const void* p) {
    uint32_t a;
    asm("{ .reg .u64 t; cvta.to.shared.u64 t, %1; cvt.u32.u64 %0, t; }" : "=r"(a) : "l"(p));
    return a;
}
__device__ __forceinline__ void ldsm_x4(uint32_t& r0, uint32_t& r1,
                                        uint32_t& r2, uint32_t& r3, uint32_t addr) {
    asm volatile("ldmatrix.sync.aligned.m8n8.x4.shared.b16 {%0,%1,%2,%3}, [%4];"
                 : "=r"(r0), "=r"(r1), "=r"(r2), "=r"(r3) : "r"(addr));
}
__device__ __forceinline__ void mma16816(float* c, const uint32_t* a, const uint32_t* b) {
    asm volatile("mma.sync.aligned.m16n8k16.row.col.f32.f16.f16.f32 "
                 "{%0,%1,%2,%3}, {%4,%5,%6,%7}, {%8,%9}, {%0,%1,%2,%3};"
                 : "+f"(c[0]), "+f"(c[1]), "+f"(c[2]), "+f"(c[3])
                 : "r"(a[0]), "r"(a[1]), "r"(a[2]), "r"(a[3]), "r"(b[0]), "r"(b[1]));
}
__device__ __forceinline__ void ins2(float& B1, int& I1, float& B2, int& I2,
                                     float v, int i) {
    if (v < B1 || (v == B1 && i < I1)) { B2 = B1; I2 = I1; B1 = v; I1 = i; }
    else if (v < B2 || (v == B2 && i < I2)) { B2 = v; I2 = i; }
}
__device__ __forceinline__ uint32_t pack_h2(float a, float b) {
    __half2 h = __floats2half2_rn(a, b);
    return *reinterpret_cast<uint32_t*>(&h);
}

// ---------------- kernel: esq + codebook fp16 hi/lo split (fused) ----------------
// one thread per code row (8192 threads)
__global__ void prep_cb_kernel(const float* __restrict__ cb) {
    int c = blockIdx.x * blockDim.x + threadIdx.x;   // 0..8191
    const float4* p = reinterpret_cast<const float4*>(cb + (size_t)c * DIM);
    uint2* ph = reinterpret_cast<uint2*>(g_Bh + (size_t)c * DIM);
    uint2* pl = reinterpret_cast<uint2*>(g_Bl + (size_t)c * DIM);
    float s = 0.f;
#pragma unroll
    for (int i = 0; i < 16; i++) {
        float4 v = p[i];
        s += v.x * v.x + v.y * v.y + v.z * v.z + v.w * v.w;
        float h0 = __half2float(__float2half_rn(v.x));
        float h1 = __half2float(__float2half_rn(v.y));
        float h2 = __half2float(__float2half_rn(v.z));
        float h3 = __half2float(__float2half_rn(v.w));
        uint2 uh, ul;
        uh.x = pack_h2(v.x, v.y);            uh.y = pack_h2(v.z, v.w);
        ul.x = pack_h2(v.x - h0, v.y - h1);  ul.y = pack_h2(v.z - h2, v.w - h3);
        ph[i] = uh;
        pl[i] = ul;
    }
    g_esq[c] = s;
}

// ---------------- main kernel: mma.sync fp16 3-pass fused + argmin ----------------
__global__ __launch_bounds__(NTHR, 2)
void vq_mma_kernel(const float* __restrict__ x,
                   const float* __restrict__ cbook,
                   float* __restrict__ out) {
    extern __shared__ char smem[];
    const uint32_t sb = smem_u32(smem);
    float* esq_s = reinterpret_cast<float*>(smem + SM_ESQ);

    const int t = threadIdx.x, wid = t >> 5, l = t & 31;
    const int mtb = blockIdx.x, kb = blockIdx.y;
    const int warp_r = wid & 3;          // 4 row groups of 32 rows
    const int warp_c = wid >> 2;         // 2 code halves of 64 codes

    // stage esq (exact fp32)
    for (int i = t; i < CB; i += NTHR) esq_s[i] = g_esq[kb * CB + i];

    // ---- stage A: x tile split to fp16 hi/lo, swizzled ----
    {
        const int r = t >> 1, h = t & 1;
        const float4* src = reinterpret_cast<const float4*>(
            x + (size_t)(mtb * MT + r) * D_FULL + kb * DIM + h * 32);
#pragma unroll
        for (int j = 0; j < 8; j++) {
            float4 v = src[j];
            float h0 = __half2float(__float2half_rn(v.x));
            float h1 = __half2float(__float2half_rn(v.y));
            float h2 = __half2float(__float2half_rn(v.z));
            float h3 = __half2float(__float2half_rn(v.w));
            uint2 uh, ul;
            uh.x = pack_h2(v.x, v.y);          uh.y = pack_h2(v.z, v.w);
            ul.x = pack_h2(v.x - h0, v.y - h1); ul.y = pack_h2(v.z - h2, v.w - h3);
            uint32_t bo = SWZ((uint32_t)(r * 128 + h * 64 + j * 8));
            *reinterpret_cast<uint2*>(smem + SM_AH + bo) = uh;
            *reinterpret_cast<uint2*>(smem + SM_AL + bo) = ul;
        }
    }
    __syncthreads();

    // ---- hoist A-hi fragments for all ks (reused across all chunks/passes) ----
    uint32_t ah[2][4][4];
#pragma unroll
    for (int ks = 0; ks < 4; ks++)
#pragma unroll
        for (int m = 0; m < 2; m++) {
            int row = warp_r * 32 + m * 16 + (l & 15);
            uint32_t ad = sb + SM_AH +
                SWZ((uint32_t)(row * 128 + ks * 32 + (l >> 4) * 16));
            ldsm_x4(ah[m][ks][0], ah[m][ks][1], ah[m][ks][2], ah[m][ks][3], ad);
        }

    float best1[4], best2[4];
    int   idx1[4], idx2[4];
#pragma unroll
    for (int s = 0; s < 4; s++) { best1[s] = 3.4e38f; best2[s] = 3.4e38f; idx1[s] = 0; idx2[s] = 0; }

#pragma unroll 1
    for (int ch = 0; ch < NCHUNK; ch++) {
        __syncthreads();
        // ---- stage B chunk: 128 codes x 64 halfs (hi + lo) ----
        {
            const uint4* srch = reinterpret_cast<const uint4*>(
                g_Bh + ((size_t)kb * CB + ch * 128) * DIM);
            const uint4* srcl = reinterpret_cast<const uint4*>(
                g_Bl + ((size_t)kb * CB + ch * 128) * DIM);
#pragma unroll
            for (int i = 0; i < 4; i++) {
                int f = t + i * NTHR;                 // 0..1023 16B units
                uint32_t bo = SWZ((uint32_t)f * 16u);
                *reinterpret_cast<uint4*>(smem + SM_BH + bo) = srch[f];
                *reinterpret_cast<uint4*>(smem + SM_BL + bo) = srcl[f];
            }
        }
        __syncthreads();

#pragma unroll 1
        for (int nh = 0; nh < 2; nh++) {              // 2 halves of 32 codes
            float acc[2][4][4];
#pragma unroll
            for (int m = 0; m < 2; m++)
#pragma unroll
                for (int n = 0; n < 4; n++)
#pragma unroll
                    for (int q = 0; q < 4; q++) acc[m][n][q] = 0.f;

#pragma unroll
            for (int ks = 0; ks < 4; ks++) {
                // B-hi and B-lo fragments for this (nh, ks)
                uint32_t bh[4][2], bl[4][2];
#pragma unroll
                for (int np = 0; np < 2; np++) {
                    int crow = warp_c * 64 + nh * 32 + np * 16 +
                               ((l >> 4) & 1) * 8 + (l & 7);
                    uint32_t off = SWZ((uint32_t)(crow * 128 + ks * 32 + ((l >> 3) & 1) * 16));
                    uint32_t r0, r1, r2, r3;
                    ldsm_x4(r0, r1, r2, r3, sb + SM_BH + off);
                    bh[np * 2][0] = r0;     bh[np * 2][1] = r1;
                    bh[np * 2 + 1][0] = r2; bh[np * 2 + 1][1] = r3;
                    ldsm_x4(r0, r1, r2, r3, sb + SM_BL + off);
                    bl[np * 2][0] = r0;     bl[np * 2][1] = r1;
                    bl[np * 2 + 1][0] = r2; bl[np * 2 + 1][1] = r3;
                }
                // A-lo fragments for this ks (streamed)
                uint32_t al[2][4];
#pragma unroll
                for (int m = 0; m < 2; m++) {
                    int row = warp_r * 32 + m * 16 + (l & 15);
                    uint32_t ad = sb + SM_AL +
                        SWZ((uint32_t)(row * 128 + ks * 32 + (l >> 4) * 16));
                    ldsm_x4(al[m][0], al[m][1], al[m][2], al[m][3], ad);
                }
                // 24 MMAs: hh + hl + lh into one accumulator
#pragma unroll
                for (int m = 0; m < 2; m++)
#pragma unroll
                    for (int n = 0; n < 4; n++) {
                        mma16816(acc[m][n], ah[m][ks], bh[n]);
                        mma16816(acc[m][n], ah[m][ks], bl[n]);
                        mma16816(acc[m][n], al[m],     bh[n]);
                    }
            }

            // ---- scoring: dist = esq - 2*dot; running top-2 per row slot ----
#pragma unroll
            for (int m = 0; m < 2; m++)
#pragma unroll
                for (int n = 0; n < 4; n++) {
                    int cbase = ch * 128 + warp_c * 64 + nh * 32 + n * 8 + 2 * (l & 3);
                    float e0 = esq_s[cbase], e1 = esq_s[cbase + 1];
                    const int s0 = 2 * m, s1 = 2 * m + 1;
                    float v;
                    v = fmaf(-2.f, acc[m][n][0], e0);
                    ins2(best1[s0], idx1[s0], best2[s0], idx2[s0], v, cbase);
                    v = fmaf(-2.f, acc[m][n][1], e1);
                    ins2(best1[s0], idx1[s0], best2[s0], idx2[s0], v, cbase + 1);
                    v = fmaf(-2.f, acc[m][n][2], e0);
                    ins2(best1[s1], idx1[s1], best2[s1], idx2[s1], v, cbase);
                    v = fmaf(-2.f, acc[m][n][3], e1);
                    ins2(best1[s1], idx1[s1], best2[s1], idx2[s1], v, cbase + 1);
                }
        }
    }

    // ---- reduce top-2 across the 4 lanes of each quad (l&3) ----
#pragma unroll
    for (int s = 0; s < 4; s++) {
#pragma unroll
        for (int m = 1; m <= 2; m <<= 1) {
            float ob1 = __shfl_xor_sync(0xffffffffu, best1[s], m);
            int   oi1 = __shfl_xor_sync(0xffffffffu, idx1[s], m);
            float ob2 = __shfl_xor_sync(0xffffffffu, best2[s], m);
            int   oi2 = __shfl_xor_sync(0xffffffffu, idx2[s], m);
            ins2(best1[s], idx1[s], best2[s], idx2[s], ob1, oi1);
            ins2(best1[s], idx1[s], best2[s], idx2[s], ob2, oi2);
        }
    }
    __syncthreads();
    float* mb1 = reinterpret_cast<float*>(smem + SM_MB1);
    int*   mi1 = reinterpret_cast<int*>  (smem + SM_MI1);
    float* mb2 = reinterpret_cast<float*>(smem + SM_MB2);
    int*   mi2 = reinterpret_cast<int*>  (smem + SM_MI2);
    if ((l & 3) == 0) {
#pragma unroll
        for (int s = 0; s < 4; s++) {
            int row = warp_r * 32 + (s >> 1) * 16 + (s & 1) * 8 + (l >> 2);
            mb1[warp_c * 128 + row] = best1[s];  mi1[warp_c * 128 + row] = idx1[s];
            mb2[warp_c * 128 + row] = best2[s];  mi2[warp_c * 128 + row] = idx2[s];
        }
    }
    __syncthreads();

    // ---- per-row epilogue (threads 0..127) ----
    float csum = 0.f;
    if (t < MT) {
        float B1 = mb1[t], B2 = mb2[t];
        int   I1 = mi1[t], I2 = mi2[t];
        ins2(B1, I1, B2, I2, mb1[128 + t], mi1[128 + t]);
        ins2(B1, I1, B2, I2, mb2[128 + t], mi2[128 + t]);

        const int row_g = mtb * MT + t;
        const float4* xp = reinterpret_cast<const float4*>(
            x + (size_t)row_g * D_FULL + kb * DIM);
        float4 xr[16];
#pragma unroll
        for (int i = 0; i < 16; i++) xr[i] = xp[i];

        // near-tie safety: exact fp32 rescore of top-2 (approx err ~1e-5 << 1e-3)
        if (B2 - B1 < 1e-3f) {
            const float* base = cbook + (size_t)kb * CB * DIM;
            float d1 = 0.f, d2 = 0.f;
            const float4* p1 = reinterpret_cast<const float4*>(base + (size_t)I1 * DIM);
            const float4* p2 = reinterpret_cast<const float4*>(base + (size_t)I2 * DIM);
#pragma unroll
            for (int i = 0; i < 16; i++) {
                float4 e1 = p1[i], e2 = p2[i];
                d1 = fmaf(xr[i].x, e1.x, d1); d1 = fmaf(xr[i].y, e1.y, d1);
                d1 = fmaf(xr[i].z, e1.z, d1); d1 = fmaf(xr[i].w, e1.w, d1);
                d2 = fmaf(xr[i].x, e2.x, d2); d2 = fmaf(xr[i].y, e2.y, d2);
                d2 = fmaf(xr[i].z, e2.z, d2); d2 = fmaf(xr[i].w, e2.w, d2);
            }
            float s1 = fmaf(-2.f, d1, esq_s[I1]);
            float s2 = fmaf(-2.f, d2, esq_s[I2]);
            if (s2 < s1 || (s2 == s1 && I2 < I1)) I1 = I2;
        }

        out[INDS_OFF + (size_t)row_g * KB + kb] = (float)I1;

        const float4* ep = reinterpret_cast<const float4*>(
            cbook + ((size_t)kb * CB + I1) * DIM);
        float4* op = reinterpret_cast<float4*>(
            out + (size_t)row_g * D_FULL + kb * DIM);
#pragma unroll
        for (int i = 0; i < 16; i++) {
            float4 e = ep[i];
            op[i] = e;
            float dx = xr[i].x - e.x, dy = xr[i].y - e.y;
            float dz = xr[i].z - e.z, dw = xr[i].w - e.w;
            csum += dx * dx + dy * dy + dz * dz + dw * dw;
        }
    }

    // deterministic commit-partial block reduce
    float* s_red = reinterpret_cast<float*>(smem + SM_RED);
    s_red[t] = csum;
    __syncthreads();
    for (int s = NTHR / 2; s > 0; s >>= 1) {
        if (t < s) s_red[t] += s_red[t + s];
        __syncthreads();
    }
    if (t == 0) g_part[kb * NMT + mtb] = s_red[0];
}

// ---------------- kernel: commit reduce ----------------
__global__ void commit_reduce(float* __restrict__ out) {
    __shared__ float s[NMT];
    const int kb = blockIdx.x;
    const int t  = threadIdx.x;      // 64 threads
    s[t] = g_part[kb * NMT + t];
    __syncthreads();
    for (int st = NMT / 2; st > 0; st >>= 1) {
        if (t < st) s[t] += s[t + st];
        __syncthreads();
    }
    if (t == 0)
        out[COMMIT_OFF + kb] = s[0] * (1.0f / (float)(ROWS * DIM));
}

extern "C" void kernel_launch(void* const* d_in, const int* in_sizes, int n_in,
                              void* d_out, int out_size) {
    const float* x  = (const float*)d_in[0];   // [4,2048,512]
    const float* cb = (const float*)d_in[1];   // [8,1024,64]
    float* out = (float*)d_out;
    (void)in_sizes; (void)n_in; (void)out_size;

    cudaFuncSetAttribute(vq_mma_kernel,
                         cudaFuncAttributeMaxDynamicSharedMemorySize, SM_TOTAL);

    prep_cb_kernel<<<(KB * CB) / 128, 128>>>(cb);
    vq_mma_kernel<<<dim3(NMT, KB), NTHR, SM_TOTAL>>>(x, cb, out);
    commit_reduce<<<KB, NMT>>>(out);
}

// round 7
// speedup vs baseline: 1.0987x; 1.0987x over previous
#include <cuda_runtime.h>
#include <cuda_fp16.h>
#include <cstdint>

// ---------------- problem constants ----------------
#define KB      8
#define DIM     64
#define CB      1024
#define ROWS    8192
#define D_FULL  512
#define MT      128              // rows per CTA
#define NMT     (ROWS/MT)        // 64
#define NTHR    256
#define NCHUNK  8                // code chunks of 128

#define CODES_ELEMS (ROWS*KB*DIM)            // 4194304
#define INDS_OFF    CODES_ELEMS
#define COMMIT_OFF  (CODES_ELEMS + ROWS*KB)  // 4259840

// ---------------- device scratch ----------------
__device__ float  g_esq[KB*CB];
__device__ float  g_part[KB*NMT];
__device__ __half g_Bh[(size_t)KB*CB*DIM];   // 1 MB
__device__ __half g_Bl[(size_t)KB*CB*DIM];   // 1 MB

// ---------------- smem layout (bytes, dynamic) ----------------
#define SM_ESQ   0                 // 4096
#define SM_AH    4096              // 16384
#define SM_BH    20480             // 16384
#define SM_BL    36864             // 16384
#define SM_MB1   53248             // 2*128 floats
#define SM_MI1   54272
#define SM_MB2   55296
#define SM_MI2   56320
#define SM_RED   57344             // 256 floats
#define SM_TOTAL 58368

#define SWZ(bo) ((bo) ^ (((bo) >> 3) & 0x70))

// ---------------- helpers ----------------
__device__ __forceinline__ uint32_t smem_u32(const void* p) {
    uint32_t a;
    asm("{ .reg .u64 t; cvta.to.shared.u64 t, %1; cvt.u32.u64 %0, t; }" : "=r"(a) : "l"(p));
    return a;
}
__device__ __forceinline__ void ldsm_x4(uint32_t& r0, uint32_t& r1,
                                        uint32_t& r2, uint32_t& r3, uint32_t addr) {
    asm volatile("ldmatrix.sync.aligned.m8n8.x4.shared.b16 {%0,%1,%2,%3}, [%4];"
                 : "=r"(r0), "=r"(r1), "=r"(r2), "=r"(r3) : "r"(addr));
}
__device__ __forceinline__ void mma16816(float* c, const uint32_t* a, const uint32_t* b) {
    asm volatile("mma.sync.aligned.m16n8k16.row.col.f32.f16.f16.f32 "
                 "{%0,%1,%2,%3}, {%4,%5,%6,%7}, {%8,%9}, {%0,%1,%2,%3};"
                 : "+f"(c[0]), "+f"(c[1]), "+f"(c[2]), "+f"(c[3])
                 : "r"(a[0]), "r"(a[1]), "r"(a[2]), "r"(a[3]), "r"(b[0]), "r"(b[1]));
}
__device__ __forceinline__ void ins2(float& B1, int& I1, float& B2, int& I2,
                                     float v, int i) {
    if (v < B1 || (v == B1 && i < I1)) { B2 = B1; I2 = I1; B1 = v; I1 = i; }
    else if (v < B2 || (v == B2 && i < I2)) { B2 = v; I2 = i; }
}
__device__ __forceinline__ uint32_t pack_h2(float a, float b) {
    __half2 h = __floats2half2_rn(a, b);
    return *reinterpret_cast<uint32_t*>(&h);
}

// ---------------- kernel: esq + codebook fp16 hi/lo split (fused) ----------------
__global__ void prep_cb_kernel(const float* __restrict__ cb) {
    int c = blockIdx.x * blockDim.x + threadIdx.x;   // 0..8191
    const float4* p = reinterpret_cast<const float4*>(cb + (size_t)c * DIM);
    uint2* ph = reinterpret_cast<uint2*>(g_Bh + (size_t)c * DIM);
    uint2* pl = reinterpret_cast<uint2*>(g_Bl + (size_t)c * DIM);
    float s = 0.f;
#pragma unroll
    for (int i = 0; i < 16; i++) {
        float4 v = p[i];
        s += v.x * v.x + v.y * v.y + v.z * v.z + v.w * v.w;
        float h0 = __half2float(__float2half_rn(v.x));
        float h1 = __half2float(__float2half_rn(v.y));
        float h2 = __half2float(__float2half_rn(v.z));
        float h3 = __half2float(__float2half_rn(v.w));
        uint2 uh, ul;
        uh.x = pack_h2(v.x, v.y);            uh.y = pack_h2(v.z, v.w);
        ul.x = pack_h2(v.x - h0, v.y - h1);  ul.y = pack_h2(v.z - h2, v.w - h3);
        ph[i] = uh;
        pl[i] = ul;
    }
    g_esq[c] = s;
}

// ---------------- main kernel: mma.sync fp16 2-pass + argmin ----------------
__global__ __launch_bounds__(NTHR, 2)
void vq_mma_kernel(const float* __restrict__ x,
                   const float* __restrict__ cbook,
                   float* __restrict__ out) {
    extern __shared__ char smem[];
    const uint32_t sb = smem_u32(smem);
    float* esq_s = reinterpret_cast<float*>(smem + SM_ESQ);

    const int t = threadIdx.x, wid = t >> 5, l = t & 31;
    const int mtb = blockIdx.x, kb = blockIdx.y;
    const int warp_r = wid & 3;          // 4 row groups of 32 rows
    const int warp_c = wid >> 2;         // 2 code halves of 64 codes

    // stage esq (exact fp32)
    for (int i = t; i < CB; i += NTHR) esq_s[i] = g_esq[kb * CB + i];

    // ---- stage A: x tile as fp16-hi, swizzled ----
    {
        const int r = t >> 1, h = t & 1;
        const float4* src = reinterpret_cast<const float4*>(
            x + (size_t)(mtb * MT + r) * D_FULL + kb * DIM + h * 32);
#pragma unroll
        for (int j = 0; j < 8; j++) {
            float4 v = src[j];
            uint2 uh;
            uh.x = pack_h2(v.x, v.y);
            uh.y = pack_h2(v.z, v.w);
            uint32_t bo = SWZ((uint32_t)(r * 128 + h * 64 + j * 8));
            *reinterpret_cast<uint2*>(smem + SM_AH + bo) = uh;
        }
    }

    float best1[4], best2[4];
    int   idx1[4], idx2[4];
#pragma unroll
    for (int s = 0; s < 4; s++) { best1[s] = 3.4e38f; best2[s] = 3.4e38f; idx1[s] = 0; idx2[s] = 0; }

#pragma unroll 1
    for (int ch = 0; ch < NCHUNK; ch++) {
        __syncthreads();
        // ---- stage B chunk: 128 codes x 64 halfs (hi + lo) ----
        {
            const uint4* srch = reinterpret_cast<const uint4*>(
                g_Bh + ((size_t)kb * CB + ch * 128) * DIM);
            const uint4* srcl = reinterpret_cast<const uint4*>(
                g_Bl + ((size_t)kb * CB + ch * 128) * DIM);
#pragma unroll
            for (int i = 0; i < 4; i++) {
                int f = t + i * NTHR;                 // 0..1023 16B units
                uint32_t bo = SWZ((uint32_t)f * 16u);
                *reinterpret_cast<uint4*>(smem + SM_BH + bo) = srch[f];
                *reinterpret_cast<uint4*>(smem + SM_BL + bo) = srcl[f];
            }
        }
        __syncthreads();

#pragma unroll 1
        for (int nh = 0; nh < 2; nh++) {              // 2 halves of 32 codes
            float acc[2][4][4];
#pragma unroll
            for (int m = 0; m < 2; m++)
#pragma unroll
                for (int n = 0; n < 4; n++)
#pragma unroll
                    for (int q = 0; q < 4; q++) acc[m][n][q] = 0.f;

            // pass 0: xh * eh ; pass 1: xh * el   (xl*e dropped; rescore covers it)
#pragma unroll
            for (int pass = 0; pass < 2; pass++) {
                const uint32_t bbase = sb + ((pass == 1) ? SM_BL : SM_BH);
#pragma unroll
                for (int ks = 0; ks < 4; ks++) {
                    uint32_t a[2][4];
#pragma unroll
                    for (int m = 0; m < 2; m++) {
                        int row = warp_r * 32 + m * 16 + (l & 15);
                        uint32_t ad = sb + SM_AH +
                            SWZ((uint32_t)(row * 128 + ks * 32 + (l >> 4) * 16));
                        ldsm_x4(a[m][0], a[m][1], a[m][2], a[m][3], ad);
                    }
                    uint32_t b[4][2];
#pragma unroll
                    for (int np = 0; np < 2; np++) {
                        int crow = warp_c * 64 + nh * 32 + np * 16 +
                                   ((l >> 4) & 1) * 8 + (l & 7);
                        uint32_t bd = bbase +
                            SWZ((uint32_t)(crow * 128 + ks * 32 + ((l >> 3) & 1) * 16));
                        uint32_t r0, r1, r2, r3;
                        ldsm_x4(r0, r1, r2, r3, bd);
                        b[np * 2][0] = r0;     b[np * 2][1] = r1;
                        b[np * 2 + 1][0] = r2; b[np * 2 + 1][1] = r3;
                    }
#pragma unroll
                    for (int m = 0; m < 2; m++)
#pragma unroll
                        for (int n = 0; n < 4; n++)
                            mma16816(acc[m][n], a[m], b[n]);
                }
            }

            // ---- scoring: dist = esq - 2*dot; running top-2 per row slot ----
#pragma unroll
            for (int m = 0; m < 2; m++)
#pragma unroll
                for (int n = 0; n < 4; n++) {
                    int cbase = ch * 128 + warp_c * 64 + nh * 32 + n * 8 + 2 * (l & 3);
                    float e0 = esq_s[cbase], e1 = esq_s[cbase + 1];
                    const int s0 = 2 * m, s1 = 2 * m + 1;
                    float v;
                    v = fmaf(-2.f, acc[m][n][0], e0);
                    ins2(best1[s0], idx1[s0], best2[s0], idx2[s0], v, cbase);
                    v = fmaf(-2.f, acc[m][n][1], e1);
                    ins2(best1[s0], idx1[s0], best2[s0], idx2[s0], v, cbase + 1);
                    v = fmaf(-2.f, acc[m][n][2], e0);
                    ins2(best1[s1], idx1[s1], best2[s1], idx2[s1], v, cbase);
                    v = fmaf(-2.f, acc[m][n][3], e1);
                    ins2(best1[s1], idx1[s1], best2[s1], idx2[s1], v, cbase + 1);
                }
        }
    }

    // ---- reduce top-2 across the 4 lanes of each quad (l&3) ----
#pragma unroll
    for (int s = 0; s < 4; s++) {
#pragma unroll
        for (int m = 1; m <= 2; m <<= 1) {
            float ob1 = __shfl_xor_sync(0xffffffffu, best1[s], m);
            int   oi1 = __shfl_xor_sync(0xffffffffu, idx1[s], m);
            float ob2 = __shfl_xor_sync(0xffffffffu, best2[s], m);
            int   oi2 = __shfl_xor_sync(0xffffffffu, idx2[s], m);
            ins2(best1[s], idx1[s], best2[s], idx2[s], ob1, oi1);
            ins2(best1[s], idx1[s], best2[s], idx2[s], ob2, oi2);
        }
    }
    __syncthreads();
    float* mb1 = reinterpret_cast<float*>(smem + SM_MB1);
    int*   mi1 = reinterpret_cast<int*>  (smem + SM_MI1);
    float* mb2 = reinterpret_cast<float*>(smem + SM_MB2);
    int*   mi2 = reinterpret_cast<int*>  (smem + SM_MI2);
    if ((l & 3) == 0) {
#pragma unroll
        for (int s = 0; s < 4; s++) {
            int row = warp_r * 32 + (s >> 1) * 16 + (s & 1) * 8 + (l >> 2);
            mb1[warp_c * 128 + row] = best1[s];  mi1[warp_c * 128 + row] = idx1[s];
            mb2[warp_c * 128 + row] = best2[s];  mi2[warp_c * 128 + row] = idx2[s];
        }
    }
    __syncthreads();

    // ---- per-row epilogue (threads 0..127) ----
    float csum = 0.f;
    if (t < MT) {
        float B1 = mb1[t], B2 = mb2[t];
        int   I1 = mi1[t], I2 = mi2[t];
        ins2(B1, I1, B2, I2, mb1[128 + t], mi1[128 + t]);
        ins2(B1, I1, B2, I2, mb2[128 + t], mi2[128 + t]);

        const int row_g = mtb * MT + t;
        const float4* xp = reinterpret_cast<const float4*>(
            x + (size_t)row_g * D_FULL + kb * DIM);
        float4 xr[16];
#pragma unroll
        for (int i = 0; i < 16; i++) xr[i] = xp[i];

        // near-tie safety: exact fp32 rescore of top-2
        // (2-pass approx err sigma ~3.5e-3 << 0.03 threshold)
        if (B2 - B1 < 0.03f) {
            const float* base = cbook + (size_t)kb * CB * DIM;
            float d1 = 0.f, d2 = 0.f;
            const float4* p1 = reinterpret_cast<const float4*>(base + (size_t)I1 * DIM);
            const float4* p2 = reinterpret_cast<const float4*>(base + (size_t)I2 * DIM);
#pragma unroll
            for (int i = 0; i < 16; i++) {
                float4 e1 = p1[i], e2 = p2[i];
                d1 = fmaf(xr[i].x, e1.x, d1); d1 = fmaf(xr[i].y, e1.y, d1);
                d1 = fmaf(xr[i].z, e1.z, d1); d1 = fmaf(xr[i].w, e1.w, d1);
                d2 = fmaf(xr[i].x, e2.x, d2); d2 = fmaf(xr[i].y, e2.y, d2);
                d2 = fmaf(xr[i].z, e2.z, d2); d2 = fmaf(xr[i].w, e2.w, d2);
            }
            float s1 = fmaf(-2.f, d1, esq_s[I1]);
            float s2 = fmaf(-2.f, d2, esq_s[I2]);
            if (s2 < s1 || (s2 == s1 && I2 < I1)) I1 = I2;
        }

        out[INDS_OFF + (size_t)row_g * KB + kb] = (float)I1;

        const float4* ep = reinterpret_cast<const float4*>(
            cbook + ((size_t)kb * CB + I1) * DIM);
        float4* op = reinterpret_cast<float4*>(
            out + (size_t)row_g * D_FULL + kb * DIM);
#pragma unroll
        for (int i = 0; i < 16; i++) {
            float4 e = ep[i];
            op[i] = e;
            float dx = xr[i].x - e.x, dy = xr[i].y - e.y;
            float dz = xr[i].z - e.z, dw = xr[i].w - e.w;
            csum += dx * dx + dy * dy + dz * dz + dw * dw;
        }
    }

    // deterministic commit-partial block reduce
    float* s_red = reinterpret_cast<float*>(smem + SM_RED);
    s_red[t] = csum;
    __syncthreads();
    for (int s = NTHR / 2; s > 0; s >>= 1) {
        if (t < s) s_red[t] += s_red[t + s];
        __syncthreads();
    }
    if (t == 0) g_part[kb * NMT + mtb] = s_red[0];
}

// ---------------- kernel: commit reduce ----------------
__global__ void commit_reduce(float* __restrict__ out) {
    __shared__ float s[NMT];
    const int kb = blockIdx.x;
    const int t  = threadIdx.x;      // 64 threads
    s[t] = g_part[kb * NMT + t];
    __syncthreads();
    for (int st = NMT / 2; st > 0; st >>= 1) {
        if (t < st) s[t] += s[t + st];
        __syncthreads();
    }
    if (t == 0)
        out[COMMIT_OFF + kb] = s[0] * (1.0f / (float)(ROWS * DIM));
}

extern "C" void kernel_launch(void* const* d_in, const int* in_sizes, int n_in,
                              void* d_out, int out_size) {
    const float* x  = (const float*)d_in[0];   // [4,2048,512]
    const float* cb = (const float*)d_in[1];   // [8,1024,64]
    float* out = (float*)d_out;
    (void)in_sizes; (void)n_in; (void)out_size;

    cudaFuncSetAttribute(vq_mma_kernel,
                         cudaFuncAttributeMaxDynamicSharedMemorySize, SM_TOTAL);

    prep_cb_kernel<<<(KB * CB) / 128, 128>>>(cb);
    vq_mma_kernel<<<dim3(NMT, KB), NTHR, SM_TOTAL>>>(x, cb, out);
    commit_reduce<<<KB, NMT>>>(out);
}

// round 8
// speedup vs baseline: 1.1149x; 1.0147x over previous
#include <cuda_runtime.h>
#include <cuda_fp16.h>
#include <cstdint>

// ---------------- problem constants ----------------
#define KB      8
#define DIM     64
#define CB      1024
#define ROWS    8192
#define D_FULL  512
#define MT      128              // rows per CTA
#define NMT     (ROWS/MT)        // 64
#define NTHR    256
#define NCHUNK  8                // code chunks of 128

#define CODES_ELEMS (ROWS*KB*DIM)            // 4194304
#define INDS_OFF    CODES_ELEMS
#define COMMIT_OFF  (CODES_ELEMS + ROWS*KB)  // 4259840

// ---------------- device scratch ----------------
__device__ float  g_esq[KB*CB];
__device__ float  g_part[KB*NMT];
__device__ __half g_Bh[(size_t)KB*CB*DIM];   // 1 MB
__device__ __half g_Bl[(size_t)KB*CB*DIM];   // 1 MB

// ---------------- smem layout (bytes, dynamic) ----------------
#define SM_ESQ    0                 // 4096
#define SM_AH     4096              // 16384
#define SM_B      20480             // 2 stages x 32768 (BH 16K + BL 16K each)
#define SM_MB1    86016             // 2*128 floats
#define SM_MI1    87040
#define SM_MB2    88064
#define SM_MI2    89088
#define SM_RED    90112             // 256 floats
#define SM_TOTAL  91136

#define SWZ(bo) ((bo) ^ (((bo) >> 3) & 0x70))

// ---------------- helpers ----------------
__device__ __forceinline__ uint32_t smem_u32(const void* p) {
    uint32_t a;
    asm("{ .reg .u64 t; cvta.to.shared.u64 t, %1; cvt.u32.u64 %0, t; }" : "=r"(a) : "l"(p));
    return a;
}
__device__ __forceinline__ void cp16(uint32_t saddr, const void* gptr) {
    asm volatile("cp.async.cg.shared.global [%0], [%1], 16;"
                 :: "r"(saddr), "l"(gptr) : "memory");
}
#define CP_COMMIT() asm volatile("cp.async.commit_group;" ::: "memory")
#define CP_WAIT(n)  asm volatile("cp.async.wait_group %0;" :: "n"(n) : "memory")

__device__ __forceinline__ void ldsm_x4(uint32_t& r0, uint32_t& r1,
                                        uint32_t& r2, uint32_t& r3, uint32_t addr) {
    asm volatile("ldmatrix.sync.aligned.m8n8.x4.shared.b16 {%0,%1,%2,%3}, [%4];"
                 : "=r"(r0), "=r"(r1), "=r"(r2), "=r"(r3) : "r"(addr));
}
__device__ __forceinline__ void mma16816(float* c, const uint32_t* a, const uint32_t* b) {
    asm volatile("mma.sync.aligned.m16n8k16.row.col.f32.f16.f16.f32 "
                 "{%0,%1,%2,%3}, {%4,%5,%6,%7}, {%8,%9}, {%0,%1,%2,%3};"
                 : "+f"(c[0]), "+f"(c[1]), "+f"(c[2]), "+f"(c[3])
                 : "r"(a[0]), "r"(a[1]), "r"(a[2]), "r"(a[3]), "r"(b[0]), "r"(b[1]));
}
__device__ __forceinline__ void ins2(float& B1, int& I1, float& B2, int& I2,
                                     float v, int i) {
    if (v < B1 || (v == B1 && i < I1)) { B2 = B1; I2 = I1; B1 = v; I1 = i; }
    else if (v < B2 || (v == B2 && i < I2)) { B2 = v; I2 = i; }
}
__device__ __forceinline__ uint32_t pack_h2(float a, float b) {
    __half2 h = __floats2half2_rn(a, b);
    return *reinterpret_cast<uint32_t*>(&h);
}

// ---------------- kernel: esq + codebook fp16 hi/lo split (fused) ----------------
__global__ void prep_cb_kernel(const float* __restrict__ cb) {
    int c = blockIdx.x * blockDim.x + threadIdx.x;   // 0..8191
    const float4* p = reinterpret_cast<const float4*>(cb + (size_t)c * DIM);
    uint2* ph = reinterpret_cast<uint2*>(g_Bh + (size_t)c * DIM);
    uint2* pl = reinterpret_cast<uint2*>(g_Bl + (size_t)c * DIM);
    float s = 0.f;
#pragma unroll
    for (int i = 0; i < 16; i++) {
        float4 v = p[i];
        s += v.x * v.x + v.y * v.y + v.z * v.z + v.w * v.w;
        float h0 = __half2float(__float2half_rn(v.x));
        float h1 = __half2float(__float2half_rn(v.y));
        float h2 = __half2float(__float2half_rn(v.z));
        float h3 = __half2float(__float2half_rn(v.w));
        uint2 uh, ul;
        uh.x = pack_h2(v.x, v.y);            uh.y = pack_h2(v.z, v.w);
        ul.x = pack_h2(v.x - h0, v.y - h1);  ul.y = pack_h2(v.z - h2, v.w - h3);
        ph[i] = uh;
        pl[i] = ul;
    }
    g_esq[c] = s;
}

// ---------------- main kernel: cp.async pipelined fp16 2-pass + argmin ----------
__global__ __launch_bounds__(NTHR, 2)
void vq_mma_kernel(const float* __restrict__ x,
                   const float* __restrict__ cbook,
                   float* __restrict__ out) {
    extern __shared__ char smem[];
    const uint32_t sb = smem_u32(smem);
    float* esq_s = reinterpret_cast<float*>(smem + SM_ESQ);

    const int t = threadIdx.x, wid = t >> 5, l = t & 31;
    const int mtb = blockIdx.x, kb = blockIdx.y;
    const int warp_r = wid & 3;          // 4 row groups of 32 rows
    const int warp_c = wid >> 2;         // 2 code halves of 64 codes

    // ---- prefetch chunk 0 (B hi+lo) via cp.async ----
    {
        const char* gh = reinterpret_cast<const char*>(g_Bh + (size_t)kb * CB * DIM);
        const char* gl = reinterpret_cast<const char*>(g_Bl + (size_t)kb * CB * DIM);
#pragma unroll
        for (int i = 0; i < 4; i++) {
            int f = t + i * NTHR;
            uint32_t bo = SWZ((uint32_t)f * 16u);
            cp16(sb + SM_B + bo, gh + (size_t)f * 16);
            cp16(sb + SM_B + 16384 + bo, gl + (size_t)f * 16);
        }
        CP_COMMIT();
    }

    // stage esq (exact fp32)
    for (int i = t; i < CB; i += NTHR) esq_s[i] = g_esq[kb * CB + i];

    // ---- stage A: x tile as fp16-hi, swizzled ----
    {
        const int r = t >> 1, h = t & 1;
        const float4* src = reinterpret_cast<const float4*>(
            x + (size_t)(mtb * MT + r) * D_FULL + kb * DIM + h * 32);
#pragma unroll
        for (int j = 0; j < 8; j++) {
            float4 v = src[j];
            uint2 uh;
            uh.x = pack_h2(v.x, v.y);
            uh.y = pack_h2(v.z, v.w);
            uint32_t bo = SWZ((uint32_t)(r * 128 + h * 64 + j * 8));
            *reinterpret_cast<uint2*>(smem + SM_AH + bo) = uh;
        }
    }

    float best1[4], best2[4];
    int   idx1[4], idx2[4];
#pragma unroll
    for (int s = 0; s < 4; s++) { best1[s] = 3.4e38f; best2[s] = 3.4e38f; idx1[s] = 0; idx2[s] = 0; }

#pragma unroll 1
    for (int ch = 0; ch < NCHUNK; ch++) {
        const uint32_t stg = sb + SM_B + (uint32_t)(ch & 1) * 32768u;
        // issue prefetch of chunk ch+1 into the other stage, then wait for ch
        if (ch < NCHUNK - 1) {
            const uint32_t nstg = sb + SM_B + (uint32_t)((ch + 1) & 1) * 32768u;
            const char* gh = reinterpret_cast<const char*>(
                g_Bh + ((size_t)kb * CB + (ch + 1) * 128) * DIM);
            const char* gl = reinterpret_cast<const char*>(
                g_Bl + ((size_t)kb * CB + (ch + 1) * 128) * DIM);
#pragma unroll
            for (int i = 0; i < 4; i++) {
                int f = t + i * NTHR;
                uint32_t bo = SWZ((uint32_t)f * 16u);
                cp16(nstg + bo, gh + (size_t)f * 16);
                cp16(nstg + 16384 + bo, gl + (size_t)f * 16);
            }
            CP_COMMIT();
            CP_WAIT(1);
        } else {
            CP_WAIT(0);
        }
        __syncthreads();

#pragma unroll 1
        for (int nh = 0; nh < 2; nh++) {              // 2 halves of 32 codes
            float acc[2][4][4];
#pragma unroll
            for (int m = 0; m < 2; m++)
#pragma unroll
                for (int n = 0; n < 4; n++)
#pragma unroll
                    for (int q = 0; q < 4; q++) acc[m][n][q] = 0.f;

            // pass 0: xh * eh ; pass 1: xh * el   (xl*e dropped; rescore covers it)
#pragma unroll
            for (int pass = 0; pass < 2; pass++) {
                const uint32_t bbase = stg + ((pass == 1) ? 16384u : 0u);
#pragma unroll
                for (int ks = 0; ks < 4; ks++) {
                    uint32_t a[2][4];
#pragma unroll
                    for (int m = 0; m < 2; m++) {
                        int row = warp_r * 32 + m * 16 + (l & 15);
                        uint32_t ad = sb + SM_AH +
                            SWZ((uint32_t)(row * 128 + ks * 32 + (l >> 4) * 16));
                        ldsm_x4(a[m][0], a[m][1], a[m][2], a[m][3], ad);
                    }
                    uint32_t b[4][2];
#pragma unroll
                    for (int np = 0; np < 2; np++) {
                        int crow = warp_c * 64 + nh * 32 + np * 16 +
                                   ((l >> 4) & 1) * 8 + (l & 7);
                        uint32_t bd = bbase +
                            SWZ((uint32_t)(crow * 128 + ks * 32 + ((l >> 3) & 1) * 16));
                        uint32_t r0, r1, r2, r3;
                        ldsm_x4(r0, r1, r2, r3, bd);
                        b[np * 2][0] = r0;     b[np * 2][1] = r1;
                        b[np * 2 + 1][0] = r2; b[np * 2 + 1][1] = r3;
                    }
#pragma unroll
                    for (int m = 0; m < 2; m++)
#pragma unroll
                        for (int n = 0; n < 4; n++)
                            mma16816(acc[m][n], a[m], b[n]);
                }
            }

            // ---- scoring: dist = esq - 2*dot; running top-2 per row slot ----
#pragma unroll
            for (int m = 0; m < 2; m++)
#pragma unroll
                for (int n = 0; n < 4; n++) {
                    int cbase = ch * 128 + warp_c * 64 + nh * 32 + n * 8 + 2 * (l & 3);
                    float e0 = esq_s[cbase], e1 = esq_s[cbase + 1];
                    const int s0 = 2 * m, s1 = 2 * m + 1;
                    float v;
                    v = fmaf(-2.f, acc[m][n][0], e0);
                    ins2(best1[s0], idx1[s0], best2[s0], idx2[s0], v, cbase);
                    v = fmaf(-2.f, acc[m][n][1], e1);
                    ins2(best1[s0], idx1[s0], best2[s0], idx2[s0], v, cbase + 1);
                    v = fmaf(-2.f, acc[m][n][2], e0);
                    ins2(best1[s1], idx1[s1], best2[s1], idx2[s1], v, cbase);
                    v = fmaf(-2.f, acc[m][n][3], e1);
                    ins2(best1[s1], idx1[s1], best2[s1], idx2[s1], v, cbase + 1);
                }
        }
        __syncthreads();   // all warps done reading stage before it is overwritten
    }

    // ---- reduce top-2 across the 4 lanes of each quad (l&3) ----
#pragma unroll
    for (int s = 0; s < 4; s++) {
#pragma unroll
        for (int m = 1; m <= 2; m <<= 1) {
            float ob1 = __shfl_xor_sync(0xffffffffu, best1[s], m);
            int   oi1 = __shfl_xor_sync(0xffffffffu, idx1[s], m);
            float ob2 = __shfl_xor_sync(0xffffffffu, best2[s], m);
            int   oi2 = __shfl_xor_sync(0xffffffffu, idx2[s], m);
            ins2(best1[s], idx1[s], best2[s], idx2[s], ob1, oi1);
            ins2(best1[s], idx1[s], best2[s], idx2[s], ob2, oi2);
        }
    }
    __syncthreads();
    float* mb1 = reinterpret_cast<float*>(smem + SM_MB1);
    int*   mi1 = reinterpret_cast<int*>  (smem + SM_MI1);
    float* mb2 = reinterpret_cast<float*>(smem + SM_MB2);
    int*   mi2 = reinterpret_cast<int*>  (smem + SM_MI2);
    if ((l & 3) == 0) {
#pragma unroll
        for (int s = 0; s < 4; s++) {
            int row = warp_r * 32 + (s >> 1) * 16 + (s & 1) * 8 + (l >> 2);
            mb1[warp_c * 128 + row] = best1[s];  mi1[warp_c * 128 + row] = idx1[s];
            mb2[warp_c * 128 + row] = best2[s];  mi2[warp_c * 128 + row] = idx2[s];
        }
    }
    __syncthreads();

    // ---- per-row epilogue (threads 0..127) ----
    float csum = 0.f;
    if (t < MT) {
        float B1 = mb1[t], B2 = mb2[t];
        int   I1 = mi1[t], I2 = mi2[t];
        ins2(B1, I1, B2, I2, mb1[128 + t], mi1[128 + t]);
        ins2(B1, I1, B2, I2, mb2[128 + t], mi2[128 + t]);

        const int row_g = mtb * MT + t;
        const float4* xp = reinterpret_cast<const float4*>(
            x + (size_t)row_g * D_FULL + kb * DIM);
        float4 xr[16];
#pragma unroll
        for (int i = 0; i < 16; i++) xr[i] = xp[i];

        // near-tie safety: exact fp32 rescore of top-2
        // (2-pass approx err sigma ~3.5e-3 << 0.03 threshold)
        if (B2 - B1 < 0.03f) {
            const float* base = cbook + (size_t)kb * CB * DIM;
            float d1 = 0.f, d2 = 0.f;
            const float4* p1 = reinterpret_cast<const float4*>(base + (size_t)I1 * DIM);
            const float4* p2 = reinterpret_cast<const float4*>(base + (size_t)I2 * DIM);
#pragma unroll
            for (int i = 0; i < 16; i++) {
                float4 e1 = p1[i], e2 = p2[i];
                d1 = fmaf(xr[i].x, e1.x, d1); d1 = fmaf(xr[i].y, e1.y, d1);
                d1 = fmaf(xr[i].z, e1.z, d1); d1 = fmaf(xr[i].w, e1.w, d1);
                d2 = fmaf(xr[i].x, e2.x, d2); d2 = fmaf(xr[i].y, e2.y, d2);
                d2 = fmaf(xr[i].z, e2.z, d2); d2 = fmaf(xr[i].w, e2.w, d2);
            }
            float s1 = fmaf(-2.f, d1, esq_s[I1]);
            float s2 = fmaf(-2.f, d2, esq_s[I2]);
            if (s2 < s1 || (s2 == s1 && I2 < I1)) I1 = I2;
        }

        out[INDS_OFF + (size_t)row_g * KB + kb] = (float)I1;

        const float4* ep = reinterpret_cast<const float4*>(
            cbook + ((size_t)kb * CB + I1) * DIM);
        float4* op = reinterpret_cast<float4*>(
            out + (size_t)row_g * D_FULL + kb * DIM);
#pragma unroll
        for (int i = 0; i < 16; i++) {
            float4 e = ep[i];
            op[i] = e;
            float dx = xr[i].x - e.x, dy = xr[i].y - e.y;
            float dz = xr[i].z - e.z, dw = xr[i].w - e.w;
            csum += dx * dx + dy * dy + dz * dz + dw * dw;
        }
    }

    // deterministic commit-partial block reduce
    float* s_red = reinterpret_cast<float*>(smem + SM_RED);
    s_red[t] = csum;
    __syncthreads();
    for (int s = NTHR / 2; s > 0; s >>= 1) {
        if (t < s) s_red[t] += s_red[t + s];
        __syncthreads();
    }
    if (t == 0) g_part[kb * NMT + mtb] = s_red[0];
}

// ---------------- kernel: commit reduce ----------------
__global__ void commit_reduce(float* __restrict__ out) {
    __shared__ float s[NMT];
    const int kb = blockIdx.x;
    const int t  = threadIdx.x;      // 64 threads
    s[t] = g_part[kb * NMT + t];
    __syncthreads();
    for (int st = NMT / 2; st > 0; st >>= 1) {
        if (t < st) s[t] += s[t + st];
        __syncthreads();
    }
    if (t == 0)
        out[COMMIT_OFF + kb] = s[0] * (1.0f / (float)(ROWS * DIM));
}

extern "C" void kernel_launch(void* const* d_in, const int* in_sizes, int n_in,
                              void* d_out, int out_size) {
    const float* x  = (const float*)d_in[0];   // [4,2048,512]
    const float* cb = (const float*)d_in[1];   // [8,1024,64]
    float* out = (float*)d_out;
    (void)in_sizes; (void)n_in; (void)out_size;

    cudaFuncSetAttribute(vq_mma_kernel,
                         cudaFuncAttributeMaxDynamicSharedMemorySize, SM_TOTAL);

    prep_cb_kernel<<<(KB * CB) / 128, 128>>>(cb);
    vq_mma_kernel<<<dim3(NMT, KB), NTHR, SM_TOTAL>>>(x, cb, out);
    commit_reduce<<<KB, NMT>>>(out);
}

// round 9
// speedup vs baseline: 1.2361x; 1.1087x over previous
#include <cuda_runtime.h>
#include <cuda_fp16.h>
#include <cstdint>

// ---------------- problem constants ----------------
#define KB      8
#define DIM     64
#define CB      1024
#define ROWS    8192
#define D_FULL  512
#define MT      128              // rows per CTA
#define NMT     (ROWS/MT)        // 64
#define NTHR    256
#define NCHUNK  8                // code chunks of 128

#define CODES_ELEMS (ROWS*KB*DIM)            // 4194304
#define INDS_OFF    CODES_ELEMS
#define COMMIT_OFF  (CODES_ELEMS + ROWS*KB)  // 4259840

// ---------------- device scratch ----------------
__device__ float  g_esq[KB*CB];
__device__ float  g_part[KB*NMT];
__device__ __half g_Bh[(size_t)KB*CB*DIM];   // 1 MB

// ---------------- smem layout (bytes, dynamic) ----------------
#define SM_ESQ    0                 // 4096
#define SM_AH     4096              // 16384
#define SM_B      20480             // 2 stages x 16384
#define SM_MB1    53248             // 2*128 floats
#define SM_MI1    54272
#define SM_MB2    55296
#define SM_MI2    56320
#define SM_RED    57344             // 256 floats
#define SM_TOTAL  58368

#define SWZ(bo) ((bo) ^ (((bo) >> 3) & 0x70))

// ---------------- helpers ----------------
__device__ __forceinline__ uint32_t smem_u32(const void* p) {
    uint32_t a;
    asm("{ .reg .u64 t; cvta.to.shared.u64 t, %1; cvt.u32.u64 %0, t; }" : "=r"(a) : "l"(p));
    return a;
}
__device__ __forceinline__ void cp16(uint32_t saddr, const void* gptr) {
    asm volatile("cp.async.cg.shared.global [%0], [%1], 16;"
                 :: "r"(saddr), "l"(gptr) : "memory");
}
#define CP_COMMIT() asm volatile("cp.async.commit_group;" ::: "memory")
#define CP_WAIT(n)  asm volatile("cp.async.wait_group %0;" :: "n"(n) : "memory")

__device__ __forceinline__ void ldsm_x4(uint32_t& r0, uint32_t& r1,
                                        uint32_t& r2, uint32_t& r3, uint32_t addr) {
    asm volatile("ldmatrix.sync.aligned.m8n8.x4.shared.b16 {%0,%1,%2,%3}, [%4];"
                 : "=r"(r0), "=r"(r1), "=r"(r2), "=r"(r3) : "r"(addr));
}
__device__ __forceinline__ void mma16816(float* c, const uint32_t* a, const uint32_t* b) {
    asm volatile("mma.sync.aligned.m16n8k16.row.col.f32.f16.f16.f32 "
                 "{%0,%1,%2,%3}, {%4,%5,%6,%7}, {%8,%9}, {%0,%1,%2,%3};"
                 : "+f"(c[0]), "+f"(c[1]), "+f"(c[2]), "+f"(c[3])
                 : "r"(a[0]), "r"(a[1]), "r"(a[2]), "r"(a[3]), "r"(b[0]), "r"(b[1]));
}
__device__ __forceinline__ void ins2(float& B1, int& I1, float& B2, int& I2,
                                     float v, int i) {
    if (v < B1 || (v == B1 && i < I1)) { B2 = B1; I2 = I1; B1 = v; I1 = i; }
    else if (v < B2 || (v == B2 && i < I2)) { B2 = v; I2 = i; }
}
__device__ __forceinline__ uint32_t pack_h2(float a, float b) {
    __half2 h = __floats2half2_rn(a, b);
    return *reinterpret_cast<uint32_t*>(&h);
}

// ---------------- kernel: esq + codebook fp16 split ----------------
__global__ void prep_cb_kernel(const float* __restrict__ cb) {
    int c = blockIdx.x * blockDim.x + threadIdx.x;   // 0..8191
    const float4* p = reinterpret_cast<const float4*>(cb + (size_t)c * DIM);
    uint2* ph = reinterpret_cast<uint2*>(g_Bh + (size_t)c * DIM);
    float s = 0.f;
#pragma unroll
    for (int i = 0; i < 16; i++) {
        float4 v = p[i];
        s += v.x * v.x + v.y * v.y + v.z * v.z + v.w * v.w;
        uint2 uh;
        uh.x = pack_h2(v.x, v.y);
        uh.y = pack_h2(v.z, v.w);
        ph[i] = uh;
    }
    g_esq[c] = s;
}

// ---------------- main kernel: cp.async pipelined fp16 1-pass + argmin ----------
__global__ __launch_bounds__(NTHR, 2)
void vq_mma_kernel(const float* __restrict__ x,
                   const float* __restrict__ cbook,
                   float* __restrict__ out) {
    extern __shared__ char smem[];
    const uint32_t sb = smem_u32(smem);
    float* esq_s = reinterpret_cast<float*>(smem + SM_ESQ);

    const int t = threadIdx.x, wid = t >> 5, l = t & 31;
    const int mtb = blockIdx.x, kb = blockIdx.y;
    const int warp_r = wid & 3;          // 4 row groups of 32 rows
    const int warp_c = wid >> 2;         // 2 code halves of 64 codes

    // ---- prefetch chunk 0 (B hi) via cp.async ----
    {
        const char* gh = reinterpret_cast<const char*>(g_Bh + (size_t)kb * CB * DIM);
#pragma unroll
        for (int i = 0; i < 4; i++) {
            int f = t + i * NTHR;
            uint32_t bo = SWZ((uint32_t)f * 16u);
            cp16(sb + SM_B + bo, gh + (size_t)f * 16);
        }
        CP_COMMIT();
    }

    // stage esq (exact fp32)
    for (int i = t; i < CB; i += NTHR) esq_s[i] = g_esq[kb * CB + i];

    // ---- stage A: x tile as fp16, swizzled ----
    {
        const int r = t >> 1, h = t & 1;
        const float4* src = reinterpret_cast<const float4*>(
            x + (size_t)(mtb * MT + r) * D_FULL + kb * DIM + h * 32);
#pragma unroll
        for (int j = 0; j < 8; j++) {
            float4 v = src[j];
            uint2 uh;
            uh.x = pack_h2(v.x, v.y);
            uh.y = pack_h2(v.z, v.w);
            uint32_t bo = SWZ((uint32_t)(r * 128 + h * 64 + j * 8));
            *reinterpret_cast<uint2*>(smem + SM_AH + bo) = uh;
        }
    }

    float best1[4], best2[4];
    int   idx1[4], idx2[4];
#pragma unroll
    for (int s = 0; s < 4; s++) { best1[s] = 3.4e38f; best2[s] = 3.4e38f; idx1[s] = 0; idx2[s] = 0; }

#pragma unroll 1
    for (int ch = 0; ch < NCHUNK; ch++) {
        const uint32_t stg = sb + SM_B + (uint32_t)(ch & 1) * 16384u;
        // issue prefetch of chunk ch+1 into the other stage, then wait for ch
        if (ch < NCHUNK - 1) {
            const uint32_t nstg = sb + SM_B + (uint32_t)((ch + 1) & 1) * 16384u;
            const char* gh = reinterpret_cast<const char*>(
                g_Bh + ((size_t)kb * CB + (ch + 1) * 128) * DIM);
#pragma unroll
            for (int i = 0; i < 4; i++) {
                int f = t + i * NTHR;
                uint32_t bo = SWZ((uint32_t)f * 16u);
                cp16(nstg + bo, gh + (size_t)f * 16);
            }
            CP_COMMIT();
            CP_WAIT(1);
        } else {
            CP_WAIT(0);
        }
        __syncthreads();

#pragma unroll 1
        for (int nh = 0; nh < 2; nh++) {              // 2 halves of 32 codes
            float acc[2][4][4];
#pragma unroll
            for (int m = 0; m < 2; m++)
#pragma unroll
                for (int n = 0; n < 4; n++)
#pragma unroll
                    for (int q = 0; q < 4; q++) acc[m][n][q] = 0.f;

            // single pass: xh * eh (residuals handled by exact top-2 rescore)
#pragma unroll
            for (int ks = 0; ks < 4; ks++) {
                uint32_t a[2][4];
#pragma unroll
                for (int m = 0; m < 2; m++) {
                    int row = warp_r * 32 + m * 16 + (l & 15);
                    uint32_t ad = sb + SM_AH +
                        SWZ((uint32_t)(row * 128 + ks * 32 + (l >> 4) * 16));
                    ldsm_x4(a[m][0], a[m][1], a[m][2], a[m][3], ad);
                }
                uint32_t b[4][2];
#pragma unroll
                for (int np = 0; np < 2; np++) {
                    int crow = warp_c * 64 + nh * 32 + np * 16 +
                               ((l >> 4) & 1) * 8 + (l & 7);
                    uint32_t bd = stg +
                        SWZ((uint32_t)(crow * 128 + ks * 32 + ((l >> 3) & 1) * 16));
                    uint32_t r0, r1, r2, r3;
                    ldsm_x4(r0, r1, r2, r3, bd);
                    b[np * 2][0] = r0;     b[np * 2][1] = r1;
                    b[np * 2 + 1][0] = r2; b[np * 2 + 1][1] = r3;
                }
#pragma unroll
                for (int m = 0; m < 2; m++)
#pragma unroll
                    for (int n = 0; n < 4; n++)
                        mma16816(acc[m][n], a[m], b[n]);
            }

            // ---- scoring: dist = esq - 2*dot; running top-2 per row slot ----
#pragma unroll
            for (int m = 0; m < 2; m++)
#pragma unroll
                for (int n = 0; n < 4; n++) {
                    int cbase = ch * 128 + warp_c * 64 + nh * 32 + n * 8 + 2 * (l & 3);
                    float e0 = esq_s[cbase], e1 = esq_s[cbase + 1];
                    const int s0 = 2 * m, s1 = 2 * m + 1;
                    float v;
                    v = fmaf(-2.f, acc[m][n][0], e0);
                    ins2(best1[s0], idx1[s0], best2[s0], idx2[s0], v, cbase);
                    v = fmaf(-2.f, acc[m][n][1], e1);
                    ins2(best1[s0], idx1[s0], best2[s0], idx2[s0], v, cbase + 1);
                    v = fmaf(-2.f, acc[m][n][2], e0);
                    ins2(best1[s1], idx1[s1], best2[s1], idx2[s1], v, cbase);
                    v = fmaf(-2.f, acc[m][n][3], e1);
                    ins2(best1[s1], idx1[s1], best2[s1], idx2[s1], v, cbase + 1);
                }
        }
        __syncthreads();   // all warps done reading stage before it is overwritten
    }

    // ---- reduce top-2 across the 4 lanes of each quad (l&3) ----
#pragma unroll
    for (int s = 0; s < 4; s++) {
#pragma unroll
        for (int m = 1; m <= 2; m <<= 1) {
            float ob1 = __shfl_xor_sync(0xffffffffu, best1[s], m);
            int   oi1 = __shfl_xor_sync(0xffffffffu, idx1[s], m);
            float ob2 = __shfl_xor_sync(0xffffffffu, best2[s], m);
            int   oi2 = __shfl_xor_sync(0xffffffffu, idx2[s], m);
            ins2(best1[s], idx1[s], best2[s], idx2[s], ob1, oi1);
            ins2(best1[s], idx1[s], best2[s], idx2[s], ob2, oi2);
        }
    }
    __syncthreads();
    float* mb1 = reinterpret_cast<float*>(smem + SM_MB1);
    int*   mi1 = reinterpret_cast<int*>  (smem + SM_MI1);
    float* mb2 = reinterpret_cast<float*>(smem + SM_MB2);
    int*   mi2 = reinterpret_cast<int*>  (smem + SM_MI2);
    if ((l & 3) == 0) {
#pragma unroll
        for (int s = 0; s < 4; s++) {
            int row = warp_r * 32 + (s >> 1) * 16 + (s & 1) * 8 + (l >> 2);
            mb1[warp_c * 128 + row] = best1[s];  mi1[warp_c * 128 + row] = idx1[s];
            mb2[warp_c * 128 + row] = best2[s];  mi2[warp_c * 128 + row] = idx2[s];
        }
    }
    __syncthreads();

    // ---- per-row epilogue (threads 0..127) ----
    float csum = 0.f;
    if (t < MT) {
        float B1 = mb1[t], B2 = mb2[t];
        int   I1 = mi1[t], I2 = mi2[t];
        ins2(B1, I1, B2, I2, mb1[128 + t], mi1[128 + t]);
        ins2(B1, I1, B2, I2, mb2[128 + t], mi2[128 + t]);

        const int row_g = mtb * MT + t;
        const float4* xp = reinterpret_cast<const float4*>(
            x + (size_t)row_g * D_FULL + kb * DIM);
        float4 xr[16];
#pragma unroll
        for (int i = 0; i < 16; i++) xr[i] = xp[i];

        // near-tie safety: exact fp32 rescore of top-2
        // (1-pass approx err sigma ~5.4e-3 << 0.08 threshold)
        if (B2 - B1 < 0.08f) {
            const float* base = cbook + (size_t)kb * CB * DIM;
            float d1 = 0.f, d2 = 0.f;
            const float4* p1 = reinterpret_cast<const float4*>(base + (size_t)I1 * DIM);
            const float4* p2 = reinterpret_cast<const float4*>(base + (size_t)I2 * DIM);
#pragma unroll
            for (int i = 0; i < 16; i++) {
                float4 e1 = p1[i], e2 = p2[i];
                d1 = fmaf(xr[i].x, e1.x, d1); d1 = fmaf(xr[i].y, e1.y, d1);
                d1 = fmaf(xr[i].z, e1.z, d1); d1 = fmaf(xr[i].w, e1.w, d1);
                d2 = fmaf(xr[i].x, e2.x, d2); d2 = fmaf(xr[i].y, e2.y, d2);
                d2 = fmaf(xr[i].z, e2.z, d2); d2 = fmaf(xr[i].w, e2.w, d2);
            }
            float s1 = fmaf(-2.f, d1, esq_s[I1]);
            float s2 = fmaf(-2.f, d2, esq_s[I2]);
            if (s2 < s1 || (s2 == s1 && I2 < I1)) I1 = I2;
        }

        out[INDS_OFF + (size_t)row_g * KB + kb] = (float)I1;

        const float4* ep = reinterpret_cast<const float4*>(
            cbook + ((size_t)kb * CB + I1) * DIM);
        float4* op = reinterpret_cast<float4*>(
            out + (size_t)row_g * D_FULL + kb * DIM);
#pragma unroll
        for (int i = 0; i < 16; i++) {
            float4 e = ep[i];
            op[i] = e;
            float dx = xr[i].x - e.x, dy = xr[i].y - e.y;
            float dz = xr[i].z - e.z, dw = xr[i].w - e.w;
            csum += dx * dx + dy * dy + dz * dz + dw * dw;
        }
    }

    // deterministic commit-partial block reduce
    float* s_red = reinterpret_cast<float*>(smem + SM_RED);
    s_red[t] = csum;
    __syncthreads();
    for (int s = NTHR / 2; s > 0; s >>= 1) {
        if (t < s) s_red[t] += s_red[t + s];
        __syncthreads();
    }
    if (t == 0) g_part[kb * NMT + mtb] = s_red[0];
}

// ---------------- kernel: commit reduce ----------------
__global__ void commit_reduce(float* __restrict__ out) {
    __shared__ float s[NMT];
    const int kb = blockIdx.x;
    const int t  = threadIdx.x;      // 64 threads
    s[t] = g_part[kb * NMT + t];
    __syncthreads();
    for (int st = NMT / 2; st > 0; st >>= 1) {
        if (t < st) s[t] += s[t + st];
        __syncthreads();
    }
    if (t == 0)
        out[COMMIT_OFF + kb] = s[0] * (1.0f / (float)(ROWS * DIM));
}

extern "C" void kernel_launch(void* const* d_in, const int* in_sizes, int n_in,
                              void* d_out, int out_size) {
    const float* x  = (const float*)d_in[0];   // [4,2048,512]
    const float* cb = (const float*)d_in[1];   // [8,1024,64]
    float* out = (float*)d_out;
    (void)in_sizes; (void)n_in; (void)out_size;

    cudaFuncSetAttribute(vq_mma_kernel,
                         cudaFuncAttributeMaxDynamicSharedMemorySize, SM_TOTAL);

    prep_cb_kernel<<<(KB * CB) / 128, 128>>>(cb);
    vq_mma_kernel<<<dim3(NMT, KB), NTHR, SM_TOTAL>>>(x, cb, out);
    commit_reduce<<<KB, NMT>>>(out);
}

// round 10
// speedup vs baseline: 2.6962x; 2.1813x over previous
#include <cuda_runtime.h>
#include <cuda_fp16.h>
#include <cstdint>

// ---------------- problem constants ----------------
#define KB      8
#define DIM     64
#define CB      1024
#define ROWS    8192
#define D_FULL  512
#define MT      128              // rows per CTA
#define NMT     (ROWS/MT)        // 64
#define NTHR    256
#define NCHUNK  8                // code chunks of 128

#define CODES_ELEMS (ROWS*KB*DIM)            // 4194304
#define INDS_OFF    CODES_ELEMS
#define COMMIT_OFF  (CODES_ELEMS + ROWS*KB)  // 4259840

// ---------------- device scratch ----------------
__device__ float  g_esq[KB*CB];
__device__ float  g_part[KB*NMT];
__device__ __half g_Bh[(size_t)KB*CB*DIM];   // 1 MB

// ---------------- smem layout (bytes, dynamic) ----------------
#define SM_ESQ    0                 // 4096
#define SM_AH     4096              // 16384
#define SM_B      20480             // 2 stages x 16384
#define SM_MB1    53248             // 2*128 floats
#define SM_MB2    54272             // 2*128 floats
#define SM_RED    55296             // 256 floats
#define SM_TOTAL  56320

#define SWZ(bo) ((bo) ^ (((bo) >> 3) & 0x70))

// ---------------- helpers ----------------
__device__ __forceinline__ uint32_t smem_u32(const void* p) {
    uint32_t a;
    asm("{ .reg .u64 t; cvta.to.shared.u64 t, %1; cvt.u32.u64 %0, t; }" : "=r"(a) : "l"(p));
    return a;
}
__device__ __forceinline__ void cp16(uint32_t saddr, const void* gptr) {
    asm volatile("cp.async.cg.shared.global [%0], [%1], 16;"
                 :: "r"(saddr), "l"(gptr) : "memory");
}
#define CP_COMMIT() asm volatile("cp.async.commit_group;" ::: "memory")
#define CP_WAIT(n)  asm volatile("cp.async.wait_group %0;" :: "n"(n) : "memory")

__device__ __forceinline__ void ldsm_x4(uint32_t& r0, uint32_t& r1,
                                        uint32_t& r2, uint32_t& r3, uint32_t addr) {
    asm volatile("ldmatrix.sync.aligned.m8n8.x4.shared.b16 {%0,%1,%2,%3}, [%4];"
                 : "=r"(r0), "=r"(r1), "=r"(r2), "=r"(r3) : "r"(addr));
}
__device__ __forceinline__ void mma16816(float* c, const uint32_t* a, const uint32_t* b) {
    asm volatile("mma.sync.aligned.m16n8k16.row.col.f32.f16.f16.f32 "
                 "{%0,%1,%2,%3}, {%4,%5,%6,%7}, {%8,%9}, {%0,%1,%2,%3};"
                 : "+f"(c[0]), "+f"(c[1]), "+f"(c[2]), "+f"(c[3])
                 : "r"(a[0]), "r"(a[1]), "r"(a[2]), "r"(a[3]), "r"(b[0]), "r"(b[1]));
}
__device__ __forceinline__ uint32_t pack_h2(float a, float b) {
    __half2 h = __floats2half2_rn(a, b);
    return *reinterpret_cast<uint32_t*>(&h);
}
// pack score with 10-bit code index in low mantissa bits (branchless argmin key)
__device__ __forceinline__ float pk(float v, int code) {
    return __uint_as_float((__float_as_uint(v) & 0xFFFFFC00u) | (uint32_t)code);
}
// branchless 2-smallest insert
__device__ __forceinline__ void min2(float& B1, float& B2, float v) {
    float lo = fminf(B1, v);
    float hi = fmaxf(B1, v);
    B1 = lo;
    B2 = fminf(B2, hi);
}
// merge two sorted pairs -> 2 smallest of 4 (branchless)
__device__ __forceinline__ void merge2(float& B1, float& B2, float o1, float o2) {
    float lo = fminf(B1, o1);
    float hi = fmaxf(B1, o1);
    B2 = fminf(fminf(B2, o2), hi);
    B1 = lo;
}

// ---------------- kernel: esq + codebook fp16 split (2 threads/code) ------------
__global__ void prep_cb_kernel(const float* __restrict__ cb) {
    int idx = blockIdx.x * blockDim.x + threadIdx.x;   // 0..16383
    int c = idx >> 1, h = idx & 1;
    const float4* p = reinterpret_cast<const float4*>(cb + (size_t)c * DIM + h * 32);
    uint2* ph = reinterpret_cast<uint2*>(g_Bh + (size_t)c * DIM + h * 32);
    float s = 0.f;
#pragma unroll
    for (int i = 0; i < 8; i++) {
        float4 v = p[i];
        s += v.x * v.x + v.y * v.y + v.z * v.z + v.w * v.w;
        uint2 uh;
        uh.x = pack_h2(v.x, v.y);
        uh.y = pack_h2(v.z, v.w);
        ph[i] = uh;
    }
    s += __shfl_xor_sync(0xffffffffu, s, 1);
    if (h == 0) g_esq[c] = s;
}

// ---------------- main kernel: cp.async pipelined fp16 1-pass + packed argmin ----
__global__ __launch_bounds__(NTHR, 2)
void vq_mma_kernel(const float* __restrict__ x,
                   const float* __restrict__ cbook,
                   float* __restrict__ out) {
    extern __shared__ char smem[];
    const uint32_t sb = smem_u32(smem);
    float* esq_s = reinterpret_cast<float*>(smem + SM_ESQ);

    const int t = threadIdx.x, wid = t >> 5, l = t & 31;
    const int mtb = blockIdx.x, kb = blockIdx.y;
    const int warp_r = wid & 3;          // 4 row groups of 32 rows
    const int warp_c = wid >> 2;         // 2 code halves of 64 codes

    // ---- prefetch chunk 0 (B hi) via cp.async ----
    {
        const char* gh = reinterpret_cast<const char*>(g_Bh + (size_t)kb * CB * DIM);
#pragma unroll
        for (int i = 0; i < 4; i++) {
            int f = t + i * NTHR;
            uint32_t bo = SWZ((uint32_t)f * 16u);
            cp16(sb + SM_B + bo, gh + (size_t)f * 16);
        }
        CP_COMMIT();
    }

    // stage esq (exact fp32)
    for (int i = t; i < CB; i += NTHR) esq_s[i] = g_esq[kb * CB + i];

    // ---- stage A: x tile as fp16, swizzled ----
    {
        const int r = t >> 1, h = t & 1;
        const float4* src = reinterpret_cast<const float4*>(
            x + (size_t)(mtb * MT + r) * D_FULL + kb * DIM + h * 32);
#pragma unroll
        for (int j = 0; j < 8; j++) {
            float4 v = src[j];
            uint2 uh;
            uh.x = pack_h2(v.x, v.y);
            uh.y = pack_h2(v.z, v.w);
            uint32_t bo = SWZ((uint32_t)(r * 128 + h * 64 + j * 8));
            *reinterpret_cast<uint2*>(smem + SM_AH + bo) = uh;
        }
    }

    float best1[4], best2[4];
#pragma unroll
    for (int s = 0; s < 4; s++) { best1[s] = 3.4e38f; best2[s] = 3.4e38f; }

#pragma unroll 1
    for (int ch = 0; ch < NCHUNK; ch++) {
        const uint32_t stg = sb + SM_B + (uint32_t)(ch & 1) * 16384u;
        // issue prefetch of chunk ch+1 into the other stage, then wait for ch
        if (ch < NCHUNK - 1) {
            const uint32_t nstg = sb + SM_B + (uint32_t)((ch + 1) & 1) * 16384u;
            const char* gh = reinterpret_cast<const char*>(
                g_Bh + ((size_t)kb * CB + (ch + 1) * 128) * DIM);
#pragma unroll
            for (int i = 0; i < 4; i++) {
                int f = t + i * NTHR;
                uint32_t bo = SWZ((uint32_t)f * 16u);
                cp16(nstg + bo, gh + (size_t)f * 16);
            }
            CP_COMMIT();
            CP_WAIT(1);
        } else {
            CP_WAIT(0);
        }
        __syncthreads();

#pragma unroll 1
        for (int nh = 0; nh < 2; nh++) {              // 2 halves of 32 codes
            float acc[2][4][4];
#pragma unroll
            for (int m = 0; m < 2; m++)
#pragma unroll
                for (int n = 0; n < 4; n++)
#pragma unroll
                    for (int q = 0; q < 4; q++) acc[m][n][q] = 0.f;

            // single pass: xh * eh (residuals handled by exact top-2 rescore)
#pragma unroll
            for (int ks = 0; ks < 4; ks++) {
                uint32_t a[2][4];
#pragma unroll
                for (int m = 0; m < 2; m++) {
                    int row = warp_r * 32 + m * 16 + (l & 15);
                    uint32_t ad = sb + SM_AH +
                        SWZ((uint32_t)(row * 128 + ks * 32 + (l >> 4) * 16));
                    ldsm_x4(a[m][0], a[m][1], a[m][2], a[m][3], ad);
                }
                uint32_t b[4][2];
#pragma unroll
                for (int np = 0; np < 2; np++) {
                    int crow = warp_c * 64 + nh * 32 + np * 16 +
                               ((l >> 4) & 1) * 8 + (l & 7);
                    uint32_t bd = stg +
                        SWZ((uint32_t)(crow * 128 + ks * 32 + ((l >> 3) & 1) * 16));
                    uint32_t r0, r1, r2, r3;
                    ldsm_x4(r0, r1, r2, r3, bd);
                    b[np * 2][0] = r0;     b[np * 2][1] = r1;
                    b[np * 2 + 1][0] = r2; b[np * 2 + 1][1] = r3;
                }
#pragma unroll
                for (int m = 0; m < 2; m++)
#pragma unroll
                    for (int n = 0; n < 4; n++)
                        mma16816(acc[m][n], a[m], b[n]);
            }

            // ---- scoring: packed (score|code), branchless 2-min network ----
#pragma unroll
            for (int m = 0; m < 2; m++)
#pragma unroll
                for (int n = 0; n < 4; n++) {
                    int cbase = ch * 128 + warp_c * 64 + nh * 32 + n * 8 + 2 * (l & 3);
                    float e0 = esq_s[cbase], e1 = esq_s[cbase + 1];
                    const int s0 = 2 * m, s1 = 2 * m + 1;
                    min2(best1[s0], best2[s0], pk(fmaf(-2.f, acc[m][n][0], e0), cbase));
                    min2(best1[s0], best2[s0], pk(fmaf(-2.f, acc[m][n][1], e1), cbase + 1));
                    min2(best1[s1], best2[s1], pk(fmaf(-2.f, acc[m][n][2], e0), cbase));
                    min2(best1[s1], best2[s1], pk(fmaf(-2.f, acc[m][n][3], e1), cbase + 1));
                }
        }
        __syncthreads();   // all warps done reading stage before it is overwritten
    }

    // ---- reduce top-2 across the 4 lanes of each quad (l&3) ----
#pragma unroll
    for (int s = 0; s < 4; s++) {
#pragma unroll
        for (int m = 1; m <= 2; m <<= 1) {
            float o1 = __shfl_xor_sync(0xffffffffu, best1[s], m);
            float o2 = __shfl_xor_sync(0xffffffffu, best2[s], m);
            merge2(best1[s], best2[s], o1, o2);
        }
    }
    __syncthreads();
    float* mb1 = reinterpret_cast<float*>(smem + SM_MB1);
    float* mb2 = reinterpret_cast<float*>(smem + SM_MB2);
    if ((l & 3) == 0) {
#pragma unroll
        for (int s = 0; s < 4; s++) {
            int row = warp_r * 32 + (s >> 1) * 16 + (s & 1) * 8 + (l >> 2);
            mb1[warp_c * 128 + row] = best1[s];
            mb2[warp_c * 128 + row] = best2[s];
        }
    }
    __syncthreads();

    // ---- per-row epilogue (threads 0..127) ----
    float csum = 0.f;
    if (t < MT) {
        float B1 = mb1[t], B2 = mb2[t];
        merge2(B1, B2, mb1[128 + t], mb2[128 + t]);
        int I1 = (int)(__float_as_uint(B1) & 1023u);
        int I2 = (int)(__float_as_uint(B2) & 1023u);

        const int row_g = mtb * MT + t;
        const float4* xp = reinterpret_cast<const float4*>(
            x + (size_t)row_g * D_FULL + kb * DIM);
        float4 xr[16];
#pragma unroll
        for (int i = 0; i < 16; i++) xr[i] = xp[i];

        // near-tie safety: exact fp32 rescore of top-2
        // (fp16 approx err ~5.4e-3 + packing noise ~0.03 << 0.15 threshold)
        if (B2 - B1 < 0.15f) {
            const float* base = cbook + (size_t)kb * CB * DIM;
            float d1 = 0.f, d2 = 0.f;
            const float4* p1 = reinterpret_cast<const float4*>(base + (size_t)I1 * DIM);
            const float4* p2 = reinterpret_cast<const float4*>(base + (size_t)I2 * DIM);
#pragma unroll
            for (int i = 0; i < 16; i++) {
                float4 e1 = p1[i], e2 = p2[i];
                d1 = fmaf(xr[i].x, e1.x, d1); d1 = fmaf(xr[i].y, e1.y, d1);
                d1 = fmaf(xr[i].z, e1.z, d1); d1 = fmaf(xr[i].w, e1.w, d1);
                d2 = fmaf(xr[i].x, e2.x, d2); d2 = fmaf(xr[i].y, e2.y, d2);
                d2 = fmaf(xr[i].z, e2.z, d2); d2 = fmaf(xr[i].w, e2.w, d2);
            }
            float s1 = fmaf(-2.f, d1, esq_s[I1]);
            float s2 = fmaf(-2.f, d2, esq_s[I2]);
            if (s2 < s1 || (s2 == s1 && I2 < I1)) I1 = I2;
        }

        out[INDS_OFF + (size_t)row_g * KB + kb] = (float)I1;

        const float4* ep = reinterpret_cast<const float4*>(
            cbook + ((size_t)kb * CB + I1) * DIM);
        float4* op = reinterpret_cast<float4*>(
            out + (size_t)row_g * D_FULL + kb * DIM);
#pragma unroll
        for (int i = 0; i < 16; i++) {
            float4 e = ep[i];
            op[i] = e;
            float dx = xr[i].x - e.x, dy = xr[i].y - e.y;
            float dz = xr[i].z - e.z, dw = xr[i].w - e.w;
            csum += dx * dx + dy * dy + dz * dz + dw * dw;
        }
    }

    // deterministic commit-partial block reduce
    float* s_red = reinterpret_cast<float*>(smem + SM_RED);
    s_red[t] = csum;
    __syncthreads();
    for (int s = NTHR / 2; s > 0; s >>= 1) {
        if (t < s) s_red[t] += s_red[t + s];
        __syncthreads();
    }
    if (t == 0) g_part[kb * NMT + mtb] = s_red[0];
}

// ---------------- kernel: commit reduce ----------------
__global__ void commit_reduce(float* __restrict__ out) {
    __shared__ float s[NMT];
    const int kb = blockIdx.x;
    const int t  = threadIdx.x;      // 64 threads
    s[t] = g_part[kb * NMT + t];
    __syncthreads();
    for (int st = NMT / 2; st > 0; st >>= 1) {
        if (t < st) s[t] += s[t + st];
        __syncthreads();
    }
    if (t == 0)
        out[COMMIT_OFF + kb] = s[0] * (1.0f / (float)(ROWS * DIM));
}

extern "C" void kernel_launch(void* const* d_in, const int* in_sizes, int n_in,
                              void* d_out, int out_size) {
    const float* x  = (const float*)d_in[0];   // [4,2048,512]
    const float* cb = (const float*)d_in[1];   // [8,1024,64]
    float* out = (float*)d_out;
    (void)in_sizes; (void)n_in; (void)out_size;

    cudaFuncSetAttribute(vq_mma_kernel,
                         cudaFuncAttributeMaxDynamicSharedMemorySize, SM_TOTAL);

    prep_cb_kernel<<<(KB * CB * 2) / 256, 256>>>(cb);
    vq_mma_kernel<<<dim3(NMT, KB), NTHR, SM_TOTAL>>>(x, cb, out);
    commit_reduce<<<KB, NMT>>>(out);
}